// round 8
// baseline (speedup 1.0000x reference)
#include <cuda_runtime.h>
#include <cuda_bf16.h>
#include <math.h>

#define BB    8
#define TENC  512
#define DIN   512
#define TDEC  150
#define ODIM  80
#define DRNN  1024
#define PRE   256
#define ATTN  128
#define LOC   32
#define KF    31

// ---------------- device scratch ----------------
__device__ float g_pm[BB * TENC * ATTN];
__device__ float g_e[BB * TENC];
__device__ float g_attcum[BB * TENC];
__device__ float g_attc[BB * TDEC * DIN];
__device__ float g_q[BB * ATTN];
__device__ float g_p2[BB * TDEC * PRE];
__device__ float g_h0[2][BB * DRNN];
__device__ float g_c0[2][BB * DRNN];
__device__ float g_h1[2][BB * DRNN];
__device__ float g_c1[2][BB * DRNN];

// ---------------- helpers ----------------
__device__ __forceinline__ float warp_sum(float v) {
    #pragma unroll
    for (int o = 16; o; o >>= 1) v += __shfl_down_sync(0xffffffffu, v, o);
    return v;
}
__device__ __forceinline__ float sigm(float x) { return 1.0f / (1.0f + __expf(-x)); }
__device__ __forceinline__ float tanh_f(float x) {
    float xc = fminf(fmaxf(x, -10.0f), 10.0f);
    float e = __expf(2.0f * xc);
    return __fdividef(e - 1.0f, e + 1.0f);
}

// ---------------- init ----------------
__global__ void init_kernel() {
    int i = blockIdx.x * 256 + threadIdx.x;
    if (i < BB * DRNN) {
        g_h0[0][i] = 0.f; g_h0[1][i] = 0.f;
        g_c0[0][i] = 0.f; g_c0[1][i] = 0.f;
        g_h1[0][i] = 0.f; g_h1[1][i] = 0.f;
        g_c1[0][i] = 0.f; g_c1[1][i] = 0.f;
    }
    if (i < BB * TENC) g_attcum[i] = 0.f;
    if (i < BB * ATTN) g_q[i] = 0.f;
}

// ---------------- processed memory: pm[b][t][a] = sum_d mem[b][t][d]*Wmem[a][d] ----------------
__global__ __launch_bounds__(256) void pm_kernel(const float* __restrict__ mem,
                                                 const float* __restrict__ Wmem) {
    int b = blockIdx.x >> 6;
    int t0 = (blockIdx.x & 63) * 8;
    __shared__ __align__(16) float sm[8 * DIN];
    const float* mptr = mem + ((size_t)b * TENC + t0) * DIN;
    for (int i = threadIdx.x; i < 8 * DIN; i += 256) sm[i] = mptr[i];
    __syncthreads();
    int w = threadIdx.x >> 5, ln = threadIdx.x & 31;
    for (int ai = 0; ai < 16; ai++) {
        int a = w * 16 + ai;
        const float4* wr = (const float4*)(Wmem + (size_t)a * DIN);
        float acc[8] = {0,0,0,0,0,0,0,0};
        #pragma unroll
        for (int it = 0; it < 4; it++) {
            float4 wv = wr[ln + it * 32];
            #pragma unroll
            for (int t = 0; t < 8; t++) {
                float4 hv = *(const float4*)(sm + t * DIN + (ln + it * 32) * 4);
                acc[t] += wv.x*hv.x + wv.y*hv.y + wv.z*hv.z + wv.w*hv.w;
            }
        }
        #pragma unroll
        for (int t = 0; t < 8; t++) {
            float v = warp_sum(acc[t]);
            if (ln == 0) g_pm[((size_t)(b * TENC) + (t0 + t)) * ATTN + a] = v;
        }
    }
}

// ---------------- prenet (both layers) for all (b, step) ----------------
__global__ __launch_bounds__(256) void prenet_kernel(const float* __restrict__ tgt,
        const float* __restrict__ W1, const float* __restrict__ b1,
        const float* __restrict__ W2, const float* __restrict__ b2) {
    int b = blockIdx.x / TDEC, s = blockIdx.x % TDEC;
    __shared__ float prev[80];
    __shared__ float p1s[PRE];
    int tid = threadIdx.x;
    if (tid < 80) prev[tid] = (s == 0) ? 0.f : tgt[((size_t)b * TDEC + (s - 1)) * ODIM + tid];
    __syncthreads();
    int w = tid >> 5, ln = tid & 31;
    for (int oi = 0; oi < 32; oi++) {
        int o = w * 32 + oi;
        float acc = 0.f;
        int k = ln * 4;
        if (k < 80) {
            float4 wv = *(const float4*)(W1 + (size_t)o * 80 + k);
            acc = wv.x*prev[k] + wv.y*prev[k+1] + wv.z*prev[k+2] + wv.w*prev[k+3];
        }
        acc = warp_sum(acc);
        if (ln == 0) p1s[o] = fmaxf(acc + b1[o], 0.f);
    }
    __syncthreads();
    for (int oi = 0; oi < 32; oi++) {
        int o = w * 32 + oi;
        float acc = 0.f;
        #pragma unroll
        for (int it = 0; it < 2; it++) {
            int k = ln * 4 + it * 128;
            float4 wv = *(const float4*)(W2 + (size_t)o * PRE + k);
            acc += wv.x*p1s[k] + wv.y*p1s[k+1] + wv.z*p1s[k+2] + wv.w*p1s[k+3];
        }
        acc = warp_sum(acc);
        if (ln == 0) g_p2[((size_t)b * TDEC + s) * PRE + o] = fmaxf(acc + b2[o], 0.f);
    }
}

// ---------------- out/stop projection for a finished step ----------------
__device__ __forceinline__ void outstop_dev(int col, int sprev, int h1buf,
        const float* __restrict__ featW, const float* __restrict__ stopW,
        const float* __restrict__ stopb, float* __restrict__ out) {
    int tid = threadIdx.x;
    int w = tid >> 5, ln = tid & 31;
    int b = w;  // 8 warps = 8 batches
    const float* wr = (col < ODIM) ? (featW + (size_t)col * 1536) : stopW;
    const float* h1p = g_h1[h1buf] + b * DRNN;
    const float* acp = g_attc + ((size_t)(b * TDEC) + sprev) * DIN;
    float acc = 0.f;
    #pragma unroll
    for (int it = 0; it < 12; it++) {
        int k = (ln + it * 32) * 4;
        float4 wv = *(const float4*)(wr + k);
        float4 zv = (k < DRNN) ? *(const float4*)(h1p + k)
                               : *(const float4*)(acp + (k - DRNN));
        acc += wv.x*zv.x + wv.y*zv.y + wv.z*zv.z + wv.w*zv.w;
    }
    acc = warp_sum(acc);
    if (ln == 0) {
        if (col < ODIM) out[((size_t)(b * TDEC) + sprev) * ODIM + col] = acc;
        else            out[BB * TDEC * ODIM + b * TDEC + sprev] = acc + stopb[0];
    }
}

// ---------------- step A: attention energies + prev-step out/stop ----------------
__global__ __launch_bounds__(256) void stepA_kernel(int s,
        const float* __restrict__ Wloc, const float* __restrict__ filt,
        const float* __restrict__ attn_v, const float* __restrict__ attn_b,
        const float* __restrict__ featW, const float* __restrict__ stopW,
        const float* __restrict__ stopb, float* __restrict__ out) {
    int bid = blockIdx.x, tid = threadIdx.x;
    if (bid >= 128) {
        if (s > 0) outstop_dev(bid - 128, s - 1, s & 1, featW, stopW, stopb, out);
        return;
    }
    __shared__ float Wl[128 * 33];
    __shared__ float fl[32 * 31];
    __shared__ float qb[128], vv[128], cum[64];
    int b = bid >> 4, t0 = (bid & 15) * 32;
    for (int i = tid; i < 4096; i += 256) { int a = i >> 5, c = i & 31; Wl[a * 33 + c] = Wloc[i]; }
    for (int i = tid; i < 992; i += 256) fl[i] = filt[i];
    if (tid < 128) { qb[tid] = g_q[b * 128 + tid] + attn_b[tid]; vv[tid] = attn_v[tid]; }
    if (tid < 64) {
        int t = t0 - 15 + tid;
        cum[tid] = (t >= 0 && t < TENC) ? g_attcum[b * TENC + t] : 0.f;
    }
    __syncthreads();
    int w = tid >> 5, ln = tid & 31;
    for (int tt = 0; tt < 4; tt++) {
        int tl = w * 4 + tt, t = t0 + tl;
        float f = 0.f;
        #pragma unroll
        for (int k = 0; k < KF; k++) f += cum[tl + k] * fl[ln * KF + k];
        float a0 = 0.f, a1 = 0.f, a2 = 0.f, a3 = 0.f;
        #pragma unroll
        for (int c = 0; c < 32; c++) {
            float fc = __shfl_sync(0xffffffffu, f, c);
            a0 += fc * Wl[(ln      ) * 33 + c];
            a1 += fc * Wl[(ln + 32 ) * 33 + c];
            a2 += fc * Wl[(ln + 64 ) * 33 + c];
            a3 += fc * Wl[(ln + 96 ) * 33 + c];
        }
        const float* pm = g_pm + ((size_t)(b * TENC) + t) * ATTN;
        float ep = vv[ln      ] * tanh_f(pm[ln      ] + a0 + qb[ln      ])
                 + vv[ln + 32 ] * tanh_f(pm[ln + 32 ] + a1 + qb[ln + 32 ])
                 + vv[ln + 64 ] * tanh_f(pm[ln + 64 ] + a2 + qb[ln + 64 ])
                 + vv[ln + 96 ] * tanh_f(pm[ln + 96 ] + a3 + qb[ln + 96 ]);
        ep = warp_sum(ep);
        if (ln == 0) g_e[b * TENC + t] = ep;
    }
}

// ---------------- step B: masked softmax + context + cum update + att_w output ----------------
__global__ __launch_bounds__(128) void stepB_kernel(int s, const float* __restrict__ mem,
                                                    const int* __restrict__ mlen,
                                                    float* __restrict__ out) {
    int b = blockIdx.x >> 2, dt = blockIdx.x & 3;
    __shared__ float wsm[TENC];
    __shared__ float red[4];
    int tid = threadIdx.x;
    int w = tid >> 5, ln = tid & 31;
    int len = mlen[b];
    const float* ep = g_e + b * TENC;
    float e0 = (tid       < len) ? ep[tid      ] : -1e9f;
    float e1 = (tid + 128 < len) ? ep[tid + 128] : -1e9f;
    float e2 = (tid + 256 < len) ? ep[tid + 256] : -1e9f;
    float e3 = (tid + 384 < len) ? ep[tid + 384] : -1e9f;
    float mx = fmaxf(fmaxf(e0, e1), fmaxf(e2, e3));
    #pragma unroll
    for (int o = 16; o; o >>= 1) mx = fmaxf(mx, __shfl_xor_sync(0xffffffffu, mx, o));
    if (ln == 0) red[w] = mx;
    __syncthreads();
    mx = fmaxf(fmaxf(red[0], red[1]), fmaxf(red[2], red[3]));
    float x0 = __expf(e0 - mx), x1 = __expf(e1 - mx);
    float x2 = __expf(e2 - mx), x3 = __expf(e3 - mx);
    float sw = warp_sum(x0 + x1 + x2 + x3);
    __syncthreads();
    if (ln == 0) red[w] = sw;
    __syncthreads();
    float inv = __fdividef(1.0f, red[0] + red[1] + red[2] + red[3]);
    wsm[tid      ] = x0 * inv;
    wsm[tid + 128] = x1 * inv;
    wsm[tid + 256] = x2 * inv;
    wsm[tid + 384] = x3 * inv;
    __syncthreads();
    // context over this 128-wide d-tile
    int d = dt * 128 + tid;
    const float* mp = mem + ((size_t)b * TENC) * DIN + d;
    float a0 = 0.f, a1 = 0.f, a2 = 0.f, a3 = 0.f;
    for (int t = 0; t < TENC; t += 4) {
        a0 += wsm[t    ] * mp[(size_t)(t    ) * DIN];
        a1 += wsm[t + 1] * mp[(size_t)(t + 1) * DIN];
        a2 += wsm[t + 2] * mp[(size_t)(t + 2) * DIN];
        a3 += wsm[t + 3] * mp[(size_t)(t + 3) * DIN];
    }
    g_attc[((size_t)(b * TDEC) + s) * DIN + d] = (a0 + a1) + (a2 + a3);
    if (dt == 0) {
        #pragma unroll
        for (int r = 0; r < 4; r++) {
            int t = tid + r * 128;
            float wv = wsm[t];
            out[BB * TDEC * ODIM + BB * TDEC + ((size_t)(b * TDEC) + s) * TENC + t] = wv;
            g_attcum[b * TENC + t] += wv;
        }
    }
}

// ---------------- step C: LSTM0 gates + zoneout update (warp per cell) ----------------
__global__ __launch_bounds__(256) void stepC_kernel(int s,
        const float* __restrict__ Wi0, const float* __restrict__ Wh0,
        const float* __restrict__ bl0) {
    extern __shared__ float xs[];   // 8 * 1792 floats = [att_c | p2 | h0] per batch
    int tid = threadIdx.x, par = s & 1, nxt = par ^ 1;
    for (int i = tid; i < 8 * 1792; i += 256) {
        int b = i / 1792, o = i - b * 1792; float v;
        if (o < 512)      v = g_attc[((size_t)(b * TDEC) + s) * DIN + o];
        else if (o < 768) v = g_p2[((size_t)(b * TDEC) + s) * PRE + (o - 512)];
        else              v = g_h0[par][b * DRNN + (o - 768)];
        xs[i] = v;
    }
    __syncthreads();
    int w = tid >> 5, ln = tid & 31;
    int j = blockIdx.x * 8 + w;
    float acc[4][8];
    #pragma unroll
    for (int g = 0; g < 4; g++)
        #pragma unroll
        for (int b = 0; b < 8; b++) acc[g][b] = 0.f;
    const float4* W0 = (const float4*)Wi0;   // rows of 192 float4
    for (int it = 0; it < 6; it++) {
        int kc = ln + it * 32;
        float4 wv[4];
        #pragma unroll
        for (int g = 0; g < 4; g++) wv[g] = W0[(size_t)(g * 1024 + j) * 192 + kc];
        #pragma unroll
        for (int b = 0; b < 8; b++) {
            float4 xv = *(const float4*)(xs + b * 1792 + kc * 4);
            #pragma unroll
            for (int g = 0; g < 4; g++)
                acc[g][b] += wv[g].x*xv.x + wv[g].y*xv.y + wv[g].z*xv.z + wv[g].w*xv.w;
        }
    }
    const float4* W1 = (const float4*)Wh0;   // rows of 256 float4
    for (int it = 0; it < 8; it++) {
        int kc = ln + it * 32;
        float4 wv[4];
        #pragma unroll
        for (int g = 0; g < 4; g++) wv[g] = W1[(size_t)(g * 1024 + j) * 256 + kc];
        #pragma unroll
        for (int b = 0; b < 8; b++) {
            float4 xv = *(const float4*)(xs + b * 1792 + 768 + kc * 4);
            #pragma unroll
            for (int g = 0; g < 4; g++)
                acc[g][b] += wv[g].x*xv.x + wv[g].y*xv.y + wv[g].z*xv.z + wv[g].w*xv.w;
        }
    }
    #pragma unroll
    for (int g = 0; g < 4; g++)
        #pragma unroll
        for (int b = 0; b < 8; b++) acc[g][b] = warp_sum(acc[g][b]);
    if (ln == 0) {
        float bi = bl0[j], bf = bl0[j + 1024], bg = bl0[j + 2048], bo = bl0[j + 3072];
        #pragma unroll
        for (int b = 0; b < 8; b++) {
            int idx = b * DRNN + j;
            float co = g_c0[par][idx], ho = g_h0[par][idx];
            float cn = sigm(acc[1][b] + bf) * co + sigm(acc[0][b] + bi) * tanh_f(acc[2][b] + bg);
            float hn = sigm(acc[3][b] + bo) * tanh_f(cn);
            g_c0[nxt][idx] = 0.9f * cn + 0.1f * co;
            g_h0[nxt][idx] = 0.9f * hn + 0.1f * ho;
        }
    }
}

// ---------------- step E: LSTM1 gates + update, plus next-step query ----------------
__global__ __launch_bounds__(256) void stepE_kernel(int s,
        const float* __restrict__ Wi1, const float* __restrict__ Wh1,
        const float* __restrict__ bl1, const float* __restrict__ Wq) {
    extern __shared__ float xs[];
    int tid = threadIdx.x, par = s & 1, nxt = par ^ 1;
    int w = tid >> 5, ln = tid & 31;
    if (blockIdx.x < 128) {
        for (int i = tid; i < 8 * 2048; i += 256) {
            int b = i >> 11, o = i & 2047;
            xs[i] = (o < 1024) ? g_h0[nxt][b * DRNN + o] : g_h1[par][b * DRNN + (o - 1024)];
        }
        __syncthreads();
        int j = blockIdx.x * 8 + w;
        float acc[4][8];
        #pragma unroll
        for (int g = 0; g < 4; g++)
            #pragma unroll
            for (int b = 0; b < 8; b++) acc[g][b] = 0.f;
        const float4* W0 = (const float4*)Wi1;
        for (int it = 0; it < 8; it++) {
            int kc = ln + it * 32;
            float4 wv[4];
            #pragma unroll
            for (int g = 0; g < 4; g++) wv[g] = W0[(size_t)(g * 1024 + j) * 256 + kc];
            #pragma unroll
            for (int b = 0; b < 8; b++) {
                float4 xv = *(const float4*)(xs + b * 2048 + kc * 4);
                #pragma unroll
                for (int g = 0; g < 4; g++)
                    acc[g][b] += wv[g].x*xv.x + wv[g].y*xv.y + wv[g].z*xv.z + wv[g].w*xv.w;
            }
        }
        const float4* W1 = (const float4*)Wh1;
        for (int it = 0; it < 8; it++) {
            int kc = ln + it * 32;
            float4 wv[4];
            #pragma unroll
            for (int g = 0; g < 4; g++) wv[g] = W1[(size_t)(g * 1024 + j) * 256 + kc];
            #pragma unroll
            for (int b = 0; b < 8; b++) {
                float4 xv = *(const float4*)(xs + b * 2048 + 1024 + kc * 4);
                #pragma unroll
                for (int g = 0; g < 4; g++)
                    acc[g][b] += wv[g].x*xv.x + wv[g].y*xv.y + wv[g].z*xv.z + wv[g].w*xv.w;
            }
        }
        #pragma unroll
        for (int g = 0; g < 4; g++)
            #pragma unroll
            for (int b = 0; b < 8; b++) acc[g][b] = warp_sum(acc[g][b]);
        if (ln == 0) {
            float bi = bl1[j], bf = bl1[j + 1024], bg = bl1[j + 2048], bo = bl1[j + 3072];
            #pragma unroll
            for (int b = 0; b < 8; b++) {
                int idx = b * DRNN + j;
                float co = g_c1[par][idx], ho = g_h1[par][idx];
                float cn = sigm(acc[1][b] + bf) * co + sigm(acc[0][b] + bi) * tanh_f(acc[2][b] + bg);
                float hn = sigm(acc[3][b] + bo) * tanh_f(cn);
                g_c1[nxt][idx] = 0.9f * cn + 0.1f * co;
                g_h1[nxt][idx] = 0.9f * hn + 0.1f * ho;
            }
        }
    } else {
        // q = h0_new @ Wq^T for next step
        for (int i = tid; i < 8192; i += 256) xs[i] = g_h0[nxt][i];
        __syncthreads();
        int a0 = (blockIdx.x - 128) * 32 + w * 4;
        float acc[4][8];
        #pragma unroll
        for (int g = 0; g < 4; g++)
            #pragma unroll
            for (int b = 0; b < 8; b++) acc[g][b] = 0.f;
        const float4* W = (const float4*)Wq;
        for (int it = 0; it < 8; it++) {
            int kc = ln + it * 32;
            float4 wv[4];
            #pragma unroll
            for (int g = 0; g < 4; g++) wv[g] = W[(size_t)(a0 + g) * 256 + kc];
            #pragma unroll
            for (int b = 0; b < 8; b++) {
                float4 xv = *(const float4*)(xs + b * 1024 + kc * 4);
                #pragma unroll
                for (int g = 0; g < 4; g++)
                    acc[g][b] += wv[g].x*xv.x + wv[g].y*xv.y + wv[g].z*xv.z + wv[g].w*xv.w;
            }
        }
        #pragma unroll
        for (int g = 0; g < 4; g++)
            #pragma unroll
            for (int b = 0; b < 8; b++) acc[g][b] = warp_sum(acc[g][b]);
        if (ln == 0) {
            #pragma unroll
            for (int g = 0; g < 4; g++)
                #pragma unroll
                for (int b = 0; b < 8; b++) g_q[b * ATTN + a0 + g] = acc[g][b];
        }
    }
}

// ---------------- final out/stop for step 149 ----------------
__global__ __launch_bounds__(256) void final_kernel(const float* __restrict__ featW,
        const float* __restrict__ stopW, const float* __restrict__ stopb,
        float* __restrict__ out) {
    // after step 149 (par=1), h1 lives in buffer 0
    outstop_dev(blockIdx.x, TDEC - 1, 0, featW, stopW, stopb, out);
}

extern "C" void kernel_launch(void* const* d_in, const int* in_sizes, int n_in,
                              void* d_out, int out_size) {
    const float* mem   = (const float*)d_in[0];
    const int*   mlen  = (const int*)  d_in[1];
    const float* tgt   = (const float*)d_in[2];
    const float* Wmem  = (const float*)d_in[3];
    const float* Wq    = (const float*)d_in[4];
    const float* Wloc  = (const float*)d_in[5];
    const float* filt  = (const float*)d_in[6];
    const float* av    = (const float*)d_in[7];
    const float* ab    = (const float*)d_in[8];
    const float* pW1   = (const float*)d_in[9];
    const float* pb1   = (const float*)d_in[10];
    const float* pW2   = (const float*)d_in[11];
    const float* pb2   = (const float*)d_in[12];
    const float* Wi0   = (const float*)d_in[13];
    const float* Wh0   = (const float*)d_in[14];
    const float* bl0   = (const float*)d_in[15];
    const float* Wi1   = (const float*)d_in[16];
    const float* Wh1   = (const float*)d_in[17];
    const float* bl1   = (const float*)d_in[18];
    const float* featW = (const float*)d_in[19];
    const float* stopW = (const float*)d_in[20];
    const float* stopb = (const float*)d_in[21];
    float* out = (float*)d_out;

    cudaFuncSetAttribute(stepC_kernel, cudaFuncAttributeMaxDynamicSharedMemorySize, 8 * 1792 * 4);
    cudaFuncSetAttribute(stepE_kernel, cudaFuncAttributeMaxDynamicSharedMemorySize, 8 * 2048 * 4);

    init_kernel<<<32, 256>>>();
    pm_kernel<<<512, 256>>>(mem, Wmem);
    prenet_kernel<<<BB * TDEC, 256>>>(tgt, pW1, pb1, pW2, pb2);

    for (int s = 0; s < TDEC; s++) {
        stepA_kernel<<<128 + ODIM + 1, 256>>>(s, Wloc, filt, av, ab, featW, stopW, stopb, out);
        stepB_kernel<<<BB * 4, 128>>>(s, mem, mlen, out);
        stepC_kernel<<<128, 256, 8 * 1792 * 4>>>(s, Wi0, Wh0, bl0);
        stepE_kernel<<<132, 256, 8 * 2048 * 4>>>(s, Wi1, Wh1, bl1, Wq);
    }
    final_kernel<<<ODIM + 1, 256>>>(featW, stopW, stopb, out);
}